// round 10
// baseline (speedup 1.0000x reference)
#include <cuda_runtime.h>
#include <cuda_fp16.h>
#include <cstdint>
#include <math.h>

#define BB 4
#define SS 2048
#define DD 2048
#define XR (BB * SS)
typedef __half h16;

// ---------------- scratch ----------------
__device__ h16  g_x16[(size_t)XR*DD];
__device__ h16  g_w16[3][(size_t)DD*DD];         // fp16 W, natural [K,N]
__device__ h16  g_QKV[3][(size_t)XR*DD];
__device__ float g_P[(size_t)BB*SS*SS];
__device__ h16  g_Ph[(size_t)BB*SS*SS];

// ---------------- helpers ----------------
__device__ __forceinline__ uint32_t smem_u32(const void* p) {
    uint32_t a;
    asm("{ .reg .u64 t; cvta.to.shared.u64 t, %1; cvt.u32.u64 %0, t; }" : "=r"(a) : "l"(p));
    return a;
}
__device__ __forceinline__ void cp16(uint32_t dst, const void* src) {
    asm volatile("cp.async.cg.shared.global [%0], [%1], 16;" :: "r"(dst), "l"(src));
}
__device__ __forceinline__ void ldm4(uint32_t* r, uint32_t addr) {
    asm volatile("ldmatrix.sync.aligned.m8n8.x4.shared.b16 {%0,%1,%2,%3}, [%4];"
                 : "=r"(r[0]), "=r"(r[1]), "=r"(r[2]), "=r"(r[3]) : "r"(addr));
}
__device__ __forceinline__ void ldm4t(uint32_t* r, uint32_t addr) {
    asm volatile("ldmatrix.sync.aligned.m8n8.x4.trans.shared.b16 {%0,%1,%2,%3}, [%4];"
                 : "=r"(r[0]), "=r"(r[1]), "=r"(r[2]), "=r"(r[3]) : "r"(addr));
}
__device__ __forceinline__ void mma_f16(float c[4], const uint32_t a[4],
                                        uint32_t b0, uint32_t b1) {
    asm volatile(
        "mma.sync.aligned.m16n8k16.row.col.f32.f16.f16.f32 "
        "{%0,%1,%2,%3}, {%4,%5,%6,%7}, {%8,%9}, {%0,%1,%2,%3};"
        : "+f"(c[0]), "+f"(c[1]), "+f"(c[2]), "+f"(c[3])
        : "r"(a[0]), "r"(a[1]), "r"(a[2]), "r"(a[3]), "r"(b0), "r"(b1));
}
__device__ __forceinline__ uint32_t pack2(h16 a, h16 b) {
    return (uint32_t)__half_as_ushort(a) | ((uint32_t)__half_as_ushort(b) << 16);
}

// ------- GEMM geometry: CTA 256x128, warps 4x2 (64x64 each), BK=32, 4 stages -------
#define RSTA 80                       // A row: 64B data + 16B pad
#define RSTBN 80                      // B [N,K] row: 64B + 16B pad
#define RSTBT 272                     // B [K,N] row: 256B + 16B pad
#define A_B (256 * RSTA)              // 20480
#define OB_OFF A_B
#define STG_NT (A_B + 128 * RSTBN)    // 30720
#define STG_TR (A_B + 32 * RSTBT)     // 29184
#define NST 4
#define SMEM_G (NST * STG_NT)         // 122880

// C[z] = alpha * A[z] @ op(B[z]);  A: [M,K] rows fp16.
// BTRANS=0: B is [N,K] rows. BTRANS=1: B is [K,N] rows (trans-ldmatrix).
// EPI 0: fp32 to Cf.  EPI 1: fp16 to Ch.
// MODE 0: dense. MODE 1: causal skip (n0 >= m0+256). MODE 2: K truncated at m0+256.
template<int EPI, int MODE, int BTRANS>
__global__ void __launch_bounds__(256, 1)
gemm_f16(const h16* __restrict__ A, const h16* __restrict__ B,
         float* __restrict__ Cf, h16* __restrict__ Ch,
         int M, int N, int K, size_t sA, size_t sB, size_t sC, float alpha)
{
    constexpr int STG_B = BTRANS ? STG_TR : STG_NT;
    int by = blockIdx.y;
    if (MODE == 1 || MODE == 2) by = gridDim.y - 1 - by;
    const int m0 = by * 256;
    const int n0 = blockIdx.x * 128;
    const int z  = blockIdx.z;
    if (MODE == 1 && n0 >= m0 + 256) return;
    int KT = K / 32;
    if (MODE == 2) { int kmax = m0 + 256; if (kmax < K) KT = kmax / 32; }

    extern __shared__ char smem[];
    const uint32_t sbase = smem_u32(smem);
    const int tid  = threadIdx.x;
    const int lane = tid & 31;
    const int wid  = tid >> 5;
    const int wm   = (wid >> 1) * 64;            // 0/64/128/192
    const int wn   = (wid & 1) * 64;             // 0/64

    const h16* pA = A + (size_t)z * sA;
    const h16* pB = B + (size_t)z * sB;

    auto load_stage = [&](int s, int kt) {
        if (kt < KT) {
            const uint32_t st = sbase + (uint32_t)s * STG_B;
            const size_t k0 = (size_t)kt * 32;
#pragma unroll
            for (int i = 0; i < 4; i++) {        // A: 256 rows x 4 segs
                const int slot = tid + i * 256;
                const int row = slot >> 2;
                const int seg = slot & 3;
                cp16(st + (uint32_t)(row * RSTA + seg * 16),
                     pA + (size_t)(m0 + row) * K + k0 + seg * 8);
            }
            if (BTRANS) {
#pragma unroll
                for (int i = 0; i < 2; i++) {    // B: 32 k-rows x 16 segs
                    const int slot = tid + i * 256;
                    const int row = slot >> 4;
                    const int seg = slot & 15;
                    cp16(st + OB_OFF + (uint32_t)(row * RSTBT + seg * 16),
                         pB + (k0 + row) * (size_t)N + n0 + seg * 8);
                }
            } else {
#pragma unroll
                for (int i = 0; i < 2; i++) {    // B: 128 n-rows x 4 segs
                    const int slot = tid + i * 256;
                    const int row = slot >> 2;
                    const int seg = slot & 3;
                    cp16(st + OB_OFF + (uint32_t)(row * RSTBN + seg * 16),
                         pB + (size_t)(n0 + row) * K + k0 + seg * 8);
                }
            }
        }
        asm volatile("cp.async.commit_group;" ::: "memory");
    };

    // ldmatrix lane addressing
    const uint32_t aoff = (uint32_t)((wm + (lane & 15)) * RSTA + (lane >> 4) * 16);
    const int nrow = (lane & 7) + ((lane >> 4) << 3);
    const int bkh  = (lane >> 3) & 1;
    const uint32_t boffN = (uint32_t)((wn + nrow) * RSTBN + bkh * 16);
    const int btrow = (lane & 7) + (((lane >> 3) & 1) << 3);
    const uint32_t boffT = (uint32_t)(btrow * RSTBT + (((lane >> 4) << 3) + wn) * 2);

    float acc[4][8][4];
#pragma unroll
    for (int i = 0; i < 4; i++)
#pragma unroll
        for (int j = 0; j < 8; j++)
#pragma unroll
            for (int q = 0; q < 4; q++) acc[i][j][q] = 0.0f;

    load_stage(0, 0);
    load_stage(1, 1);
    load_stage(2, 2);

    for (int it = 0; it < KT; it++) {
        const int s = it & (NST - 1);
        asm volatile("cp.async.wait_group 2;" ::: "memory");
        __syncthreads();
        const uint32_t stg = sbase + (uint32_t)s * STG_B;
#pragma unroll
        for (int ks = 0; ks < 2; ks++) {         // 2 x k16 slices per 32-chunk
            uint32_t a[4][4], bb[8][2];
#pragma unroll
            for (int mt = 0; mt < 4; mt++)
                ldm4(a[mt], stg + aoff + mt * (16 * RSTA) + ks * 32);
#pragma unroll
            for (int ntp = 0; ntp < 4; ntp++) {
                uint32_t t[4];
                if (BTRANS)
                    ldm4t(t, stg + OB_OFF + boffT + ks * (16 * RSTBT) + ntp * 32);
                else
                    ldm4(t, stg + OB_OFF + boffN + ntp * (16 * RSTBN) + ks * 32);
                bb[2*ntp][0] = t[0]; bb[2*ntp][1] = t[1];
                bb[2*ntp+1][0] = t[2]; bb[2*ntp+1][1] = t[3];
            }
#pragma unroll
            for (int mt = 0; mt < 4; mt++)
#pragma unroll
                for (int nt = 0; nt < 8; nt++)
                    mma_f16(acc[mt][nt], a[mt], bb[nt][0], bb[nt][1]);
        }
        load_stage((it + 3) & (NST - 1), it + 3);
    }

    // ---- epilogue ----
    const int r0 = wm + (lane >> 2);
    const int c0 = wn + (lane & 3) * 2;
#pragma unroll
    for (int mt = 0; mt < 4; mt++) {
#pragma unroll
        for (int nt = 0; nt < 8; nt++) {
            const int row = m0 + r0 + mt * 16;
            const int col = n0 + c0 + nt * 8;
            const float v0 = acc[mt][nt][0] * alpha, v1 = acc[mt][nt][1] * alpha;
            const float v2 = acc[mt][nt][2] * alpha, v3 = acc[mt][nt][3] * alpha;
            const size_t o0 = (size_t)z * sC + (size_t)row * N + col;
            const size_t o1 = (size_t)z * sC + (size_t)(row + 8) * N + col;
            if (EPI == 0) {
                Cf[o0] = v0; Cf[o0 + 1] = v1;
                Cf[o1] = v2; Cf[o1 + 1] = v3;
            } else {
                *reinterpret_cast<uint32_t*>(Ch + o0) =
                    pack2(__float2half_rn(v0), __float2half_rn(v1));
                *reinterpret_cast<uint32_t*>(Ch + o1) =
                    pack2(__float2half_rn(v2), __float2half_rn(v3));
            }
        }
    }
}

// ---------------- conversion (x + 3 W fused) / softmax ----------------
__global__ __launch_bounds__(256) void convert_all_kernel(
    const float* __restrict__ x, const float* __restrict__ W0,
    const float* __restrict__ W1, const float* __restrict__ W2,
    h16* __restrict__ x16, h16* __restrict__ w16)
{
    const int zz = blockIdx.z;
    const float* in;
    h16* out;
    size_t n4;
    if (zz == 0) { in = x;  out = x16;                          n4 = (size_t)XR * DD / 4; }
    else {
        in  = (zz == 1) ? W0 : (zz == 2) ? W1 : W2;
        out = w16 + (size_t)(zz - 1) * DD * DD;
        n4  = (size_t)DD * DD / 4;
    }
    for (size_t i = (size_t)blockIdx.x * 256 + threadIdx.x; i < n4; i += (size_t)gridDim.x * 256) {
        const float4 v = reinterpret_cast<const float4*>(in)[i];
        uint2 o;
        o.x = pack2(__float2half_rn(v.x), __float2half_rn(v.y));
        o.y = pack2(__float2half_rn(v.z), __float2half_rn(v.w));
        reinterpret_cast<uint2*>(out)[i] = o;
    }
}

__global__ __launch_bounds__(256) void softmax_kernel(
    const float* __restrict__ P, h16* __restrict__ Ph)
{
    const int row = blockIdx.x & (SS - 1);
    const int b   = blockIdx.x >> 11;
    const size_t base = ((size_t)b * SS + row) * SS;
    const int L = row + 1;
    const int tid = threadIdx.x;

    float v[8];
    float m = -INFINITY;
#pragma unroll
    for (int j = 0; j < 8; j++) {
        const int i = tid + j * 256;
        v[j] = (i < L) ? P[base + i] : -INFINITY;
        m = fmaxf(m, v[j]);
    }
    __shared__ float red[256];
    red[tid] = m; __syncthreads();
    for (int s2 = 128; s2 > 0; s2 >>= 1) {
        if (tid < s2) red[tid] = fmaxf(red[tid], red[tid + s2]);
        __syncthreads();
    }
    m = red[0]; __syncthreads();

    float sum = 0.0f;
#pragma unroll
    for (int j = 0; j < 8; j++) {
        const int i = tid + j * 256;
        if (i < L) { v[j] = __expf(v[j] - m); sum += v[j]; }
    }
    red[tid] = sum; __syncthreads();
    for (int s2 = 128; s2 > 0; s2 >>= 1) {
        if (tid < s2) red[tid] += red[tid + s2];
        __syncthreads();
    }
    const float inv = 1.0f / red[0];
    __syncthreads();

#pragma unroll
    for (int j = 0; j < 8; j++) {
        const int i = tid + j * 256;
        if (i < L) Ph[base + i] = __float2half_rn(v[j] * inv);
    }
    const h16 z16 = __ushort_as_half(0);
    for (int i = L + tid; i < SS; i += 256) Ph[base + i] = z16;
}

// ---------------- launch ----------------
extern "C" void kernel_launch(void* const* d_in, const int* in_sizes, int n_in,
                              void* d_out, int out_size)
{
    const float* x  = (const float*)d_in[0];
    const float* Wq = (const float*)d_in[1];
    const float* Wk = (const float*)d_in[2];
    const float* Wv = (const float*)d_in[3];
    float* out = (float*)d_out;

    h16 *x16, *w16, *QKV, *Ph;
    float* P;
    cudaGetSymbolAddress((void**)&x16, g_x16);
    cudaGetSymbolAddress((void**)&w16, g_w16);
    cudaGetSymbolAddress((void**)&QKV, g_QKV);
    cudaGetSymbolAddress((void**)&P,   g_P);
    cudaGetSymbolAddress((void**)&Ph,  g_Ph);

    cudaFuncSetAttribute(gemm_f16<1,0,1>, cudaFuncAttributeMaxDynamicSharedMemorySize, SMEM_G);
    cudaFuncSetAttribute(gemm_f16<0,1,0>, cudaFuncAttributeMaxDynamicSharedMemorySize, SMEM_G);
    cudaFuncSetAttribute(gemm_f16<0,2,1>, cudaFuncAttributeMaxDynamicSharedMemorySize, SMEM_G);

    const size_t WSZ = (size_t)DD * DD;
    const size_t QSZ = (size_t)XR * DD;

    // fp32 -> fp16 conversions (x and W in natural layouts)
    convert_all_kernel<<<dim3(2048, 1, 4), 256>>>(x, Wq, Wk, Wv, x16, w16);

    // QKV (fused z=3): A = x16 [M,K]; B = w16 [K,N] via trans-ldmatrix
    dim3 g1(DD/128, XR/256, 3);
    gemm_f16<1,0,1><<<g1, 256, SMEM_G>>>(x16, w16, nullptr, QKV,
                                         XR, DD, DD, 0, WSZ, QSZ, 1.0f);

    // scores: P[b] = scale * Q[b] @ K[b]^T  (K is [N,K] natural; causal skip)
    dim3 g2(SS/128, SS/256, BB);
    const float scale = 1.0f / sqrtf((float)DD);
    gemm_f16<0,1,0><<<g2, 256, SMEM_G>>>(QKV, QKV + QSZ, P, nullptr,
                                         SS, SS, DD, (size_t)SS*DD, (size_t)SS*DD,
                                         (size_t)SS*SS, scale);

    // causal softmax -> fp16 P
    softmax_kernel<<<BB * SS, 256>>>(P, Ph);

    // out[b] = P[b] @ V[b]: A = Ph [M,K]; B = V [K,N] natural via trans-ldmatrix
    dim3 g3(DD/128, SS/256, BB);
    gemm_f16<0,2,1><<<g3, 256, SMEM_G>>>(Ph, QKV + 2*QSZ, out, nullptr,
                                         SS, DD, SS, (size_t)SS*SS, (size_t)SS*DD,
                                         (size_t)SS*DD, 1.0f);
}

// round 11
// speedup vs baseline: 1.0777x; 1.0777x over previous
#include <cuda_runtime.h>
#include <cuda_fp16.h>
#include <cstdint>
#include <math.h>

#define BB 4
#define SS 2048
#define DD 2048
#define XR (BB * SS)
typedef __half h16;

// ---------------- scratch ----------------
__device__ h16  g_x16[(size_t)XR*DD];
__device__ h16  g_w16[3][(size_t)DD*DD];         // fp16 W, natural [K,N]
__device__ h16  g_QKV[3][(size_t)XR*DD];
__device__ float g_P[(size_t)BB*SS*SS];
__device__ h16  g_Ph[(size_t)BB*SS*SS];

// ---------------- helpers ----------------
__device__ __forceinline__ uint32_t smem_u32(const void* p) {
    uint32_t a;
    asm("{ .reg .u64 t; cvta.to.shared.u64 t, %1; cvt.u32.u64 %0, t; }" : "=r"(a) : "l"(p));
    return a;
}
__device__ __forceinline__ void cp16(uint32_t dst, const void* src) {
    asm volatile("cp.async.cg.shared.global [%0], [%1], 16;" :: "r"(dst), "l"(src));
}
__device__ __forceinline__ void ldm4(uint32_t* r, uint32_t addr) {
    asm volatile("ldmatrix.sync.aligned.m8n8.x4.shared.b16 {%0,%1,%2,%3}, [%4];"
                 : "=r"(r[0]), "=r"(r[1]), "=r"(r[2]), "=r"(r[3]) : "r"(addr));
}
__device__ __forceinline__ void ldm4t(uint32_t* r, uint32_t addr) {
    asm volatile("ldmatrix.sync.aligned.m8n8.x4.trans.shared.b16 {%0,%1,%2,%3}, [%4];"
                 : "=r"(r[0]), "=r"(r[1]), "=r"(r[2]), "=r"(r[3]) : "r"(addr));
}
__device__ __forceinline__ void mma_f16(float c[4], const uint32_t a[4],
                                        uint32_t b0, uint32_t b1) {
    asm volatile(
        "mma.sync.aligned.m16n8k16.row.col.f32.f16.f16.f32 "
        "{%0,%1,%2,%3}, {%4,%5,%6,%7}, {%8,%9}, {%0,%1,%2,%3};"
        : "+f"(c[0]), "+f"(c[1]), "+f"(c[2]), "+f"(c[3])
        : "r"(a[0]), "r"(a[1]), "r"(a[2]), "r"(a[3]), "r"(b0), "r"(b1));
}
__device__ __forceinline__ uint32_t pack2(h16 a, h16 b) {
    return (uint32_t)__half_as_ushort(a) | ((uint32_t)__half_as_ushort(b) << 16);
}

// ---------------- GEMM geometry: CTA 128x128, warp 64x32, BK=64, 3 stages ----
#define RST 144                       // A row: 128B data + 16B pad
#define RSTB 272                      // trans-B row: 256B data + 16B pad
#define A_B (128 * RST)               // 18432
#define OB_OFF A_B
#define STG_NT (2 * A_B)              // 36864  (B as [N,K], 128 rows x 144B)
#define STG_TR (A_B + 64 * RSTB)      // 35840  (B as [K,N], 64 rows x 272B)
#define NST 3
#define SMEM_G (NST * STG_NT)         // 110592 -> 2 CTAs/SM

// C[z] = alpha * A[z] @ op(B[z]);  A: [M,K] rows fp16.
// BTRANS=0: B is [N,K] rows (K-major). BTRANS=1: B is [K,N] rows, trans-ldmatrix.
// EPI 0: fp32 to Cf.  EPI 1: fp16 to Ch.
// MODE 0: dense. MODE 1: causal skip (n0 > m0). MODE 2: K truncated at m0+128.
// MODE 1/2 reverse blockIdx.y so heavy tiles launch first.
template<int EPI, int MODE, int BTRANS>
__global__ void __launch_bounds__(256, 2)
gemm_f16(const h16* __restrict__ A, const h16* __restrict__ B,
         float* __restrict__ Cf, h16* __restrict__ Ch,
         int M, int N, int K, size_t sA, size_t sB, size_t sC, float alpha)
{
    constexpr int STG_B = BTRANS ? STG_TR : STG_NT;
    int by = blockIdx.y;
    if (MODE == 1 || MODE == 2) by = gridDim.y - 1 - by;
    const int m0 = by * 128;
    const int n0 = blockIdx.x * 128;
    const int z  = blockIdx.z;
    if (MODE == 1 && n0 > m0) return;
    int KT = K / 64;
    if (MODE == 2) { int kmax = m0 + 128; if (kmax < K) KT = kmax / 64; }

    extern __shared__ char smem[];
    const uint32_t sbase = smem_u32(smem);
    const int tid  = threadIdx.x;
    const int lane = tid & 31;
    const int wid  = tid >> 5;
    const int wm   = (wid >> 2) * 64;
    const int wn   = (wid & 3) * 32;

    const h16* pA = A + (size_t)z * sA;
    const h16* pB = B + (size_t)z * sB;

    auto load_stage = [&](int s, int kt) {
        if (kt < KT) {
            const uint32_t st = sbase + (uint32_t)s * STG_B;
            const size_t k0 = (size_t)kt * 64;
#pragma unroll
            for (int i = 0; i < 4; i++) {          // A: 128 rows x 8 segs
                const int slot = tid + i * 256;
                const int row = slot >> 3;
                const int seg = slot & 7;
                cp16(st + (uint32_t)(row * RST + seg * 16),
                     pA + (size_t)(m0 + row) * K + k0 + seg * 8);
            }
            if (BTRANS) {
#pragma unroll
                for (int i = 0; i < 4; i++) {      // B: 64 k-rows x 16 segs
                    const int slot = tid + i * 256;
                    const int row = slot >> 4;
                    const int seg = slot & 15;
                    cp16(st + OB_OFF + (uint32_t)(row * RSTB + seg * 16),
                         pB + (k0 + row) * (size_t)N + n0 + seg * 8);
                }
            } else {
#pragma unroll
                for (int i = 0; i < 4; i++) {      // B: 128 n-rows x 8 segs
                    const int slot = tid + i * 256;
                    const int row = slot >> 3;
                    const int seg = slot & 7;
                    cp16(st + OB_OFF + (uint32_t)(row * RST + seg * 16),
                         pB + (size_t)(n0 + row) * K + k0 + seg * 8);
                }
            }
        }
        asm volatile("cp.async.commit_group;" ::: "memory");
    };

    // ldmatrix lane addressing
    const int arow = lane & 15;
    const int akh  = lane >> 4;
    const uint32_t aoff = (uint32_t)((wm + arow) * RST + akh * 16);
    // non-trans B
    const int nrow = (lane & 7) + ((lane >> 4) << 3);
    const int bkh  = (lane >> 3) & 1;
    const uint32_t boffN = (uint32_t)((wn + nrow) * RST + bkh * 16);
    // trans B: rows = k, 16B col = n-octet
    const int btrow = (lane & 7) + (((lane >> 3) & 1) << 3);
    const uint32_t boffT = (uint32_t)(btrow * RSTB + (((lane >> 4) << 3) + wn) * 2);

    float acc[4][4][4];
#pragma unroll
    for (int i = 0; i < 4; i++)
#pragma unroll
        for (int j = 0; j < 4; j++)
#pragma unroll
            for (int q = 0; q < 4; q++) acc[i][j][q] = 0.0f;

    load_stage(0, 0);
    load_stage(1, 1);

    for (int it = 0; it < KT; it++) {
        const int s = it % NST;
        asm volatile("cp.async.wait_group 1;" ::: "memory");
        __syncthreads();
        // Loads for stage (it+2)%NST == (it-1)%NST are safe now: all warps
        // finished reading it in iteration it-1 (guaranteed by the sync above).
        load_stage((it + 2) % NST, it + 2);
        const uint32_t stg = sbase + (uint32_t)s * STG_B;
#pragma unroll
        for (int ks = 0; ks < 4; ks++) {
            uint32_t a[4][4], b[4][2];
#pragma unroll
            for (int mt = 0; mt < 4; mt++)
                ldm4(a[mt], stg + aoff + mt * (16 * RST) + ks * 32);
#pragma unroll
            for (int ntp = 0; ntp < 2; ntp++) {
                uint32_t t[4];
                if (BTRANS)
                    ldm4t(t, stg + OB_OFF + boffT + ks * (16 * RSTB) + ntp * 32);
                else
                    ldm4(t, stg + OB_OFF + boffN + ntp * (16 * RST) + ks * 32);
                b[2*ntp][0] = t[0]; b[2*ntp][1] = t[1];
                b[2*ntp+1][0] = t[2]; b[2*ntp+1][1] = t[3];
            }
#pragma unroll
            for (int mt = 0; mt < 4; mt++)
#pragma unroll
                for (int nt = 0; nt < 4; nt++)
                    mma_f16(acc[mt][nt], a[mt], b[nt][0], b[nt][1]);
        }
    }

    // ---- epilogue ----
    const int r0 = wm + (lane >> 2);
    const int c0 = wn + (lane & 3) * 2;
#pragma unroll
    for (int mt = 0; mt < 4; mt++) {
#pragma unroll
        for (int nt = 0; nt < 4; nt++) {
            const int row = m0 + r0 + mt * 16;
            const int col = n0 + c0 + nt * 8;
            const float v0 = acc[mt][nt][0] * alpha, v1 = acc[mt][nt][1] * alpha;
            const float v2 = acc[mt][nt][2] * alpha, v3 = acc[mt][nt][3] * alpha;
            const size_t o0 = (size_t)z * sC + (size_t)row * N + col;
            const size_t o1 = (size_t)z * sC + (size_t)(row + 8) * N + col;
            if (EPI == 0) {
                Cf[o0] = v0; Cf[o0 + 1] = v1;
                Cf[o1] = v2; Cf[o1 + 1] = v3;
            } else {
                *reinterpret_cast<uint32_t*>(Ch + o0) =
                    pack2(__float2half_rn(v0), __float2half_rn(v1));
                *reinterpret_cast<uint32_t*>(Ch + o1) =
                    pack2(__float2half_rn(v2), __float2half_rn(v3));
            }
        }
    }
}

// ---------------- conversion (x + 3 W fused) / softmax ----------------
__global__ __launch_bounds__(256) void convert_all_kernel(
    const float* __restrict__ x, const float* __restrict__ W0,
    const float* __restrict__ W1, const float* __restrict__ W2,
    h16* __restrict__ x16, h16* __restrict__ w16)
{
    const int zz = blockIdx.z;
    const float* in;
    h16* out;
    size_t n4;
    if (zz == 0) { in = x;  out = x16;                          n4 = (size_t)XR * DD / 4; }
    else {
        in  = (zz == 1) ? W0 : (zz == 2) ? W1 : W2;
        out = w16 + (size_t)(zz - 1) * DD * DD;
        n4  = (size_t)DD * DD / 4;
    }
    for (size_t i = (size_t)blockIdx.x * 256 + threadIdx.x; i < n4; i += (size_t)gridDim.x * 256) {
        const float4 v = reinterpret_cast<const float4*>(in)[i];
        uint2 o;
        o.x = pack2(__float2half_rn(v.x), __float2half_rn(v.y));
        o.y = pack2(__float2half_rn(v.z), __float2half_rn(v.w));
        reinterpret_cast<uint2*>(out)[i] = o;
    }
}

// causal softmax, warp-shuffle reductions, float4 I/O.
// One block of 256 threads per row (row length SS=2048 -> 2 float4 per thread).
__global__ __launch_bounds__(256) void softmax_kernel(
    const float* __restrict__ P, h16* __restrict__ Ph)
{
    const int row = blockIdx.x & (SS - 1);
    const int b   = blockIdx.x >> 11;
    const size_t base = ((size_t)b * SS + row) * SS;
    const int L = row + 1;
    const int tid  = threadIdx.x;
    const int lane = tid & 31;
    const int wrp  = tid >> 5;

    const float4* P4 = reinterpret_cast<const float4*>(P + base);
    float4 va = P4[tid];
    float4 vb = P4[tid + 256];
    const int e0 = tid * 4;            // elements e0..e0+3
    const int e1 = 1024 + tid * 4;     // elements e1..e1+3

    float v[8] = {va.x, va.y, va.z, va.w, vb.x, vb.y, vb.z, vb.w};
    float m = -INFINITY;
#pragma unroll
    for (int q = 0; q < 4; q++) if (e0 + q < L) m = fmaxf(m, v[q]);
#pragma unroll
    for (int q = 0; q < 4; q++) if (e1 + q < L) m = fmaxf(m, v[4 + q]);

    __shared__ float red[8];
#pragma unroll
    for (int o = 16; o > 0; o >>= 1) m = fmaxf(m, __shfl_xor_sync(0xFFFFFFFFu, m, o));
    if (lane == 0) red[wrp] = m;
    __syncthreads();
#pragma unroll
    for (int w = 0; w < 8; w++) m = fmaxf(m, red[w]);
    __syncthreads();

    float sum = 0.0f;
#pragma unroll
    for (int q = 0; q < 4; q++) {
        v[q]     = (e0 + q < L) ? __expf(v[q] - m)     : 0.0f;
        v[4 + q] = (e1 + q < L) ? __expf(v[4 + q] - m) : 0.0f;
        sum += v[q] + v[4 + q];
    }
#pragma unroll
    for (int o = 16; o > 0; o >>= 1) sum += __shfl_xor_sync(0xFFFFFFFFu, sum, o);
    if (lane == 0) red[wrp] = sum;
    __syncthreads();
    sum = 0.0f;
#pragma unroll
    for (int w = 0; w < 8; w++) sum += red[w];
    const float inv = 1.0f / sum;

    uint2* O4 = reinterpret_cast<uint2*>(Ph + base);
    uint2 oa, ob;
    oa.x = pack2(__float2half_rn(v[0] * inv), __float2half_rn(v[1] * inv));
    oa.y = pack2(__float2half_rn(v[2] * inv), __float2half_rn(v[3] * inv));
    ob.x = pack2(__float2half_rn(v[4] * inv), __float2half_rn(v[5] * inv));
    ob.y = pack2(__float2half_rn(v[6] * inv), __float2half_rn(v[7] * inv));
    O4[tid] = oa;
    O4[tid + 256] = ob;
}

// ---------------- launch ----------------
extern "C" void kernel_launch(void* const* d_in, const int* in_sizes, int n_in,
                              void* d_out, int out_size)
{
    const float* x  = (const float*)d_in[0];
    const float* Wq = (const float*)d_in[1];
    const float* Wk = (const float*)d_in[2];
    const float* Wv = (const float*)d_in[3];
    float* out = (float*)d_out;

    h16 *x16, *w16, *QKV, *Ph;
    float* P;
    cudaGetSymbolAddress((void**)&x16, g_x16);
    cudaGetSymbolAddress((void**)&w16, g_w16);
    cudaGetSymbolAddress((void**)&QKV, g_QKV);
    cudaGetSymbolAddress((void**)&P,   g_P);
    cudaGetSymbolAddress((void**)&Ph,  g_Ph);

    cudaFuncSetAttribute(gemm_f16<1,0,1>, cudaFuncAttributeMaxDynamicSharedMemorySize, SMEM_G);
    cudaFuncSetAttribute(gemm_f16<0,1,0>, cudaFuncAttributeMaxDynamicSharedMemorySize, SMEM_G);
    cudaFuncSetAttribute(gemm_f16<0,2,1>, cudaFuncAttributeMaxDynamicSharedMemorySize, SMEM_G);

    const size_t WSZ = (size_t)DD * DD;
    const size_t QSZ = (size_t)XR * DD;

    // fp32 -> fp16 conversions (x and W in natural layouts)
    convert_all_kernel<<<dim3(2048, 1, 4), 256>>>(x, Wq, Wk, Wv, x16, w16);

    // QKV (fused z=3): A = x16 [M,K]; B = w16 [K,N] via trans-ldmatrix
    dim3 g1(DD/128, XR/128, 3);
    gemm_f16<1,0,1><<<g1, 256, SMEM_G>>>(x16, w16, nullptr, QKV,
                                         XR, DD, DD, 0, WSZ, QSZ, 1.0f);

    // scores: P[b] = scale * Q[b] @ K[b]^T  (K is [N,K] natural; causal skip)
    dim3 g2(SS/128, SS/128, BB);
    const float scale = 1.0f / sqrtf((float)DD);
    gemm_f16<0,1,0><<<g2, 256, SMEM_G>>>(QKV, QKV + QSZ, P, nullptr,
                                         SS, SS, DD, (size_t)SS*DD, (size_t)SS*DD,
                                         (size_t)SS*SS, scale);

    // causal softmax -> fp16 P
    softmax_kernel<<<BB * SS, 256>>>(P, Ph);

    // out[b] = P[b] @ V[b]: A = Ph [M,K]; B = V [K,N] natural via trans-ldmatrix
    dim3 g3(DD/128, SS/128, BB);
    gemm_f16<0,2,1><<<g3, 256, SMEM_G>>>(Ph, QKV + 2*QSZ, out, nullptr,
                                         SS, DD, SS, (size_t)SS*SS, (size_t)SS*DD,
                                         (size_t)SS*DD, 1.0f);
}

// round 12
// speedup vs baseline: 1.0830x; 1.0049x over previous
#include <cuda_runtime.h>
#include <cuda_fp16.h>
#include <cstdint>
#include <math.h>

#define BB 4
#define SS 2048
#define DD 2048
#define XR (BB * SS)
typedef __half h16;

// ---------------- scratch ----------------
__device__ h16  g_x16[(size_t)XR*DD];
__device__ h16  g_w16[3][(size_t)DD*DD];         // fp16 W, natural [K,N]
__device__ h16  g_QKV[3][(size_t)XR*DD];
__device__ float g_P[(size_t)BB*SS*SS];
__device__ h16  g_Ph[(size_t)BB*SS*SS];

// ---------------- helpers ----------------
__device__ __forceinline__ uint32_t smem_u32(const void* p) {
    uint32_t a;
    asm("{ .reg .u64 t; cvta.to.shared.u64 t, %1; cvt.u32.u64 %0, t; }" : "=r"(a) : "l"(p));
    return a;
}
__device__ __forceinline__ void cp16(uint32_t dst, const void* src) {
    asm volatile("cp.async.cg.shared.global [%0], [%1], 16;" :: "r"(dst), "l"(src));
}
__device__ __forceinline__ void ldm4(uint32_t* r, uint32_t addr) {
    asm volatile("ldmatrix.sync.aligned.m8n8.x4.shared.b16 {%0,%1,%2,%3}, [%4];"
                 : "=r"(r[0]), "=r"(r[1]), "=r"(r[2]), "=r"(r[3]) : "r"(addr));
}
__device__ __forceinline__ void ldm4t(uint32_t* r, uint32_t addr) {
    asm volatile("ldmatrix.sync.aligned.m8n8.x4.trans.shared.b16 {%0,%1,%2,%3}, [%4];"
                 : "=r"(r[0]), "=r"(r[1]), "=r"(r[2]), "=r"(r[3]) : "r"(addr));
}
__device__ __forceinline__ void mma_f16(float c[4], const uint32_t a[4],
                                        uint32_t b0, uint32_t b1) {
    asm volatile(
        "mma.sync.aligned.m16n8k16.row.col.f32.f16.f16.f32 "
        "{%0,%1,%2,%3}, {%4,%5,%6,%7}, {%8,%9}, {%0,%1,%2,%3};"
        : "+f"(c[0]), "+f"(c[1]), "+f"(c[2]), "+f"(c[3])
        : "r"(a[0]), "r"(a[1]), "r"(a[2]), "r"(a[3]), "r"(b0), "r"(b1));
}
__device__ __forceinline__ uint32_t pack2(h16 a, h16 b) {
    return (uint32_t)__half_as_ushort(a) | ((uint32_t)__half_as_ushort(b) << 16);
}
// PDL primitives (sm_90+ base PTX, valid on compute_103)
__device__ __forceinline__ void gdc_wait() {
    asm volatile("griddepcontrol.wait;" ::: "memory");
}
__device__ __forceinline__ void gdc_launch() {
    asm volatile("griddepcontrol.launch_dependents;" ::: "memory");
}

// ---------------- GEMM geometry: CTA 128x128, warp 64x32, BK=64, 3 stages ----
#define RST 144                       // A row: 128B data + 16B pad
#define RSTB 272                      // trans-B row: 256B data + 16B pad
#define A_B (128 * RST)               // 18432
#define OB_OFF A_B
#define STG_NT (2 * A_B)              // 36864  (B as [N,K], 128 rows x 144B)
#define STG_TR (A_B + 64 * RSTB)      // 35840  (B as [K,N], 64 rows x 272B)
#define NST 3
#define SMEM_G (NST * STG_NT)         // 110592 -> 2 CTAs/SM

// C[z] = alpha * A[z] @ op(B[z]);  A: [M,K] rows fp16.
// BTRANS=0: B is [N,K] rows. BTRANS=1: B is [K,N] rows (trans-ldmatrix).
// EPI 0: fp32 to Cf.  EPI 1: fp16 to Ch.
// MODE 0: dense. MODE 1: causal skip (n0 > m0). MODE 2: K truncated at m0+128.
template<int EPI, int MODE, int BTRANS>
__global__ void __launch_bounds__(256, 2)
gemm_f16(const h16* __restrict__ A, const h16* __restrict__ B,
         float* __restrict__ Cf, h16* __restrict__ Ch,
         int M, int N, int K, size_t sA, size_t sB, size_t sC, float alpha)
{
    constexpr int STG_B = BTRANS ? STG_TR : STG_NT;
    int by = blockIdx.y;
    if (MODE == 1 || MODE == 2) by = gridDim.y - 1 - by;
    const int m0 = by * 128;
    const int n0 = blockIdx.x * 128;
    const int z  = blockIdx.z;
    if (MODE == 1 && n0 > m0) { gdc_launch(); return; }
    int KT = K / 64;
    if (MODE == 2) { int kmax = m0 + 128; if (kmax < K) KT = kmax / 64; }

    extern __shared__ char smem[];
    const uint32_t sbase = smem_u32(smem);
    const int tid  = threadIdx.x;
    const int lane = tid & 31;
    const int wid  = tid >> 5;
    const int wm   = (wid >> 2) * 64;
    const int wn   = (wid & 3) * 32;

    const h16* pA = A + (size_t)z * sA;
    const h16* pB = B + (size_t)z * sB;

    auto load_stage = [&](int s, int kt) {
        if (kt < KT) {
            const uint32_t st = sbase + (uint32_t)s * STG_B;
            const size_t k0 = (size_t)kt * 64;
#pragma unroll
            for (int i = 0; i < 4; i++) {          // A: 128 rows x 8 segs
                const int slot = tid + i * 256;
                const int row = slot >> 3;
                const int seg = slot & 7;
                cp16(st + (uint32_t)(row * RST + seg * 16),
                     pA + (size_t)(m0 + row) * K + k0 + seg * 8);
            }
            if (BTRANS) {
#pragma unroll
                for (int i = 0; i < 4; i++) {      // B: 64 k-rows x 16 segs
                    const int slot = tid + i * 256;
                    const int row = slot >> 4;
                    const int seg = slot & 15;
                    cp16(st + OB_OFF + (uint32_t)(row * RSTB + seg * 16),
                         pB + (k0 + row) * (size_t)N + n0 + seg * 8);
                }
            } else {
#pragma unroll
                for (int i = 0; i < 4; i++) {      // B: 128 n-rows x 8 segs
                    const int slot = tid + i * 256;
                    const int row = slot >> 3;
                    const int seg = slot & 7;
                    cp16(st + OB_OFF + (uint32_t)(row * RST + seg * 16),
                         pB + (size_t)(n0 + row) * K + k0 + seg * 8);
                }
            }
        }
        asm volatile("cp.async.commit_group;" ::: "memory");
    };

    // ldmatrix lane addressing
    const int arow = lane & 15;
    const int akh  = lane >> 4;
    const uint32_t aoff = (uint32_t)((wm + arow) * RST + akh * 16);
    const int nrow = (lane & 7) + ((lane >> 4) << 3);
    const int bkh  = (lane >> 3) & 1;
    const uint32_t boffN = (uint32_t)((wn + nrow) * RST + bkh * 16);
    const int btrow = (lane & 7) + (((lane >> 3) & 1) << 3);
    const uint32_t boffT = (uint32_t)(btrow * RSTB + (((lane >> 4) << 3) + wn) * 2);

    float acc[4][4][4];
#pragma unroll
    for (int i = 0; i < 4; i++)
#pragma unroll
        for (int j = 0; j < 4; j++)
#pragma unroll
            for (int q = 0; q < 4; q++) acc[i][j][q] = 0.0f;

    gdc_wait();                       // upstream grid fully complete before reads
    load_stage(0, 0);
    load_stage(1, 1);

    for (int it = 0; it < KT; it++) {
        const int s = it % NST;
        asm volatile("cp.async.wait_group 1;" ::: "memory");
        __syncthreads();
        // Stage (it+2)%NST == (it-1)%NST: its readers finished before the sync above.
        load_stage((it + 2) % NST, it + 2);
        const uint32_t stg = sbase + (uint32_t)s * STG_B;
#pragma unroll
        for (int ks = 0; ks < 4; ks++) {
            uint32_t a[4][4], b[4][2];
#pragma unroll
            for (int mt = 0; mt < 4; mt++)
                ldm4(a[mt], stg + aoff + mt * (16 * RST) + ks * 32);
#pragma unroll
            for (int ntp = 0; ntp < 2; ntp++) {
                uint32_t t[4];
                if (BTRANS)
                    ldm4t(t, stg + OB_OFF + boffT + ks * (16 * RSTB) + ntp * 32);
                else
                    ldm4(t, stg + OB_OFF + boffN + ntp * (16 * RST) + ks * 32);
                b[2*ntp][0] = t[0]; b[2*ntp][1] = t[1];
                b[2*ntp+1][0] = t[2]; b[2*ntp+1][1] = t[3];
            }
#pragma unroll
            for (int mt = 0; mt < 4; mt++)
#pragma unroll
                for (int nt = 0; nt < 4; nt++)
                    mma_f16(acc[mt][nt], a[mt], b[nt][0], b[nt][1]);
        }
    }

    gdc_launch();                     // main loop done; let next grid start on freed SMs

    // ---- epilogue ----
    const int r0 = wm + (lane >> 2);
    const int c0 = wn + (lane & 3) * 2;
#pragma unroll
    for (int mt = 0; mt < 4; mt++) {
#pragma unroll
        for (int nt = 0; nt < 4; nt++) {
            const int row = m0 + r0 + mt * 16;
            const int col = n0 + c0 + nt * 8;
            const float v0 = acc[mt][nt][0] * alpha, v1 = acc[mt][nt][1] * alpha;
            const float v2 = acc[mt][nt][2] * alpha, v3 = acc[mt][nt][3] * alpha;
            const size_t o0 = (size_t)z * sC + (size_t)row * N + col;
            const size_t o1 = (size_t)z * sC + (size_t)(row + 8) * N + col;
            if (EPI == 0) {
                Cf[o0] = v0; Cf[o0 + 1] = v1;
                Cf[o1] = v2; Cf[o1 + 1] = v3;
            } else {
                *reinterpret_cast<uint32_t*>(Ch + o0) =
                    pack2(__float2half_rn(v0), __float2half_rn(v1));
                *reinterpret_cast<uint32_t*>(Ch + o1) =
                    pack2(__float2half_rn(v2), __float2half_rn(v3));
            }
        }
    }
}

// ---------------- conversion (x + 3 W fused) / softmax ----------------
__global__ __launch_bounds__(256) void convert_all_kernel(
    const float* __restrict__ x, const float* __restrict__ W0,
    const float* __restrict__ W1, const float* __restrict__ W2,
    h16* __restrict__ x16, h16* __restrict__ w16)
{
    const int zz = blockIdx.z;
    const float* in;
    h16* out;
    size_t n4;
    if (zz == 0) { in = x;  out = x16;                          n4 = (size_t)XR * DD / 4; }
    else {
        in  = (zz == 1) ? W0 : (zz == 2) ? W1 : W2;
        out = w16 + (size_t)(zz - 1) * DD * DD;
        n4  = (size_t)DD * DD / 4;
    }
    for (size_t i = (size_t)blockIdx.x * 256 + threadIdx.x; i < n4; i += (size_t)gridDim.x * 256) {
        const float4 v = reinterpret_cast<const float4*>(in)[i];
        uint2 o;
        o.x = pack2(__float2half_rn(v.x), __float2half_rn(v.y));
        o.y = pack2(__float2half_rn(v.z), __float2half_rn(v.w));
        reinterpret_cast<uint2*>(out)[i] = o;
    }
    gdc_launch();
}

// causal softmax, warp-shuffle reductions, float4 I/O. One block per row.
__global__ __launch_bounds__(256) void softmax_kernel(
    const float* __restrict__ P, h16* __restrict__ Ph)
{
    const int row = blockIdx.x & (SS - 1);
    const int b   = blockIdx.x >> 11;
    const size_t base = ((size_t)b * SS + row) * SS;
    const int L = row + 1;
    const int tid  = threadIdx.x;
    const int lane = tid & 31;
    const int wrp  = tid >> 5;

    gdc_wait();
    const float4* P4 = reinterpret_cast<const float4*>(P + base);
    float4 va = P4[tid];
    float4 vb = P4[tid + 256];
    const int e0 = tid * 4;
    const int e1 = 1024 + tid * 4;

    float v[8] = {va.x, va.y, va.z, va.w, vb.x, vb.y, vb.z, vb.w};
    float m = -INFINITY;
#pragma unroll
    for (int q = 0; q < 4; q++) if (e0 + q < L) m = fmaxf(m, v[q]);
#pragma unroll
    for (int q = 0; q < 4; q++) if (e1 + q < L) m = fmaxf(m, v[4 + q]);

    __shared__ float red[8];
#pragma unroll
    for (int o = 16; o > 0; o >>= 1) m = fmaxf(m, __shfl_xor_sync(0xFFFFFFFFu, m, o));
    if (lane == 0) red[wrp] = m;
    __syncthreads();
#pragma unroll
    for (int w = 0; w < 8; w++) m = fmaxf(m, red[w]);
    __syncthreads();

    float sum = 0.0f;
#pragma unroll
    for (int q = 0; q < 4; q++) {
        v[q]     = (e0 + q < L) ? __expf(v[q] - m)     : 0.0f;
        v[4 + q] = (e1 + q < L) ? __expf(v[4 + q] - m) : 0.0f;
        sum += v[q] + v[4 + q];
    }
#pragma unroll
    for (int o = 16; o > 0; o >>= 1) sum += __shfl_xor_sync(0xFFFFFFFFu, sum, o);
    if (lane == 0) red[wrp] = sum;
    __syncthreads();
    sum = 0.0f;
#pragma unroll
    for (int w = 0; w < 8; w++) sum += red[w];
    const float inv = 1.0f / sum;
    gdc_launch();

    uint2* O4 = reinterpret_cast<uint2*>(Ph + base);
    uint2 oa, ob;
    oa.x = pack2(__float2half_rn(v[0] * inv), __float2half_rn(v[1] * inv));
    oa.y = pack2(__float2half_rn(v[2] * inv), __float2half_rn(v[3] * inv));
    ob.x = pack2(__float2half_rn(v[4] * inv), __float2half_rn(v[5] * inv));
    ob.y = pack2(__float2half_rn(v[6] * inv), __float2half_rn(v[7] * inv));
    O4[tid] = oa;
    O4[tid + 256] = ob;
}

// ---------------- PDL launch helper ----------------
static void launch_pdl(const void* func, dim3 grid, dim3 block, size_t smem, void** args)
{
    cudaLaunchConfig_t cfg = {};
    cfg.gridDim = grid;
    cfg.blockDim = block;
    cfg.dynamicSmemBytes = smem;
    cfg.stream = 0;
    cudaLaunchAttribute attr[1];
    attr[0].id = cudaLaunchAttributeProgrammaticStreamSerialization;
    attr[0].val.programmaticStreamSerializationAllowed = 1;
    cfg.attrs = attr;
    cfg.numAttrs = 1;
    if (cudaLaunchKernelExC(&cfg, func, args) != cudaSuccess) {
        // fallback: plain launch preserves correctness
        cudaLaunchKernel(func, grid, block, args, smem, 0);
    }
}

// ---------------- launch ----------------
extern "C" void kernel_launch(void* const* d_in, const int* in_sizes, int n_in,
                              void* d_out, int out_size)
{
    const float* x  = (const float*)d_in[0];
    const float* Wq = (const float*)d_in[1];
    const float* Wk = (const float*)d_in[2];
    const float* Wv = (const float*)d_in[3];
    float* out = (float*)d_out;

    h16 *x16, *w16, *QKV, *Ph;
    float* P;
    cudaGetSymbolAddress((void**)&x16, g_x16);
    cudaGetSymbolAddress((void**)&w16, g_w16);
    cudaGetSymbolAddress((void**)&QKV, g_QKV);
    cudaGetSymbolAddress((void**)&P,   g_P);
    cudaGetSymbolAddress((void**)&Ph,  g_Ph);

    cudaFuncSetAttribute(gemm_f16<1,0,1>, cudaFuncAttributeMaxDynamicSharedMemorySize, SMEM_G);
    cudaFuncSetAttribute(gemm_f16<0,1,0>, cudaFuncAttributeMaxDynamicSharedMemorySize, SMEM_G);
    cudaFuncSetAttribute(gemm_f16<0,2,1>, cudaFuncAttributeMaxDynamicSharedMemorySize, SMEM_G);

    size_t WSZ = (size_t)DD * DD;
    size_t QSZ = (size_t)XR * DD;

    // 1. fp32 -> fp16 conversions (x and W in natural layouts)
    convert_all_kernel<<<dim3(2048, 1, 4), 256>>>(x, Wq, Wk, Wv, x16, w16);

    const float scale = 1.0f / sqrtf((float)DD);
    h16* nullh = nullptr;
    float* nullf = nullptr;

    // 2. QKV (fused z=3): A = x16 [M,K]; B = w16 [K,N] via trans-ldmatrix
    {
        int M = XR, N = DD, K = DD;
        size_t sA = 0, sB = WSZ, sC = QSZ;
        float alpha = 1.0f;
        void* args[] = {&x16, &w16, &nullf, &QKV, &M, &N, &K, &sA, &sB, &sC, &alpha};
        launch_pdl((const void*)gemm_f16<1,0,1>, dim3(DD/128, XR/128, 3), 256, SMEM_G, args);
    }

    // 3. scores: P[b] = scale * Q[b] @ K[b]^T (causal skip)
    {
        int M = SS, N = SS, K = DD;
        size_t sA = (size_t)SS*DD, sB = (size_t)SS*DD, sC = (size_t)SS*SS;
        float alpha = scale;
        const h16* Qp = QKV;
        const h16* Kp = QKV + QSZ;
        void* args[] = {&Qp, &Kp, &P, &nullh, &M, &N, &K, &sA, &sB, &sC, &alpha};
        launch_pdl((const void*)gemm_f16<0,1,0>, dim3(SS/128, SS/128, BB), 256, SMEM_G, args);
    }

    // 4. causal softmax -> fp16 P
    {
        const float* Pp = P;
        void* args[] = {&Pp, &Ph};
        launch_pdl((const void*)softmax_kernel, dim3(BB * SS), 256, 0, args);
    }

    // 5. out[b] = P[b] @ V[b] (K truncated at diagonal)
    {
        int M = SS, N = DD, K = SS;
        size_t sA = (size_t)SS*SS, sB = (size_t)SS*DD, sC = (size_t)SS*DD;
        float alpha = 1.0f;
        const h16* Pp = Ph;
        const h16* Vp = QKV + 2*QSZ;
        void* args[] = {&Pp, &Vp, &out, &nullh, &M, &N, &K, &sA, &sB, &sC, &alpha};
        launch_pdl((const void*)gemm_f16<0,2,1>, dim3(DD/128, SS/128, BB), 256, SMEM_G, args);
    }
}

// round 13
// speedup vs baseline: 1.0846x; 1.0014x over previous
#include <cuda_runtime.h>
#include <cuda_fp16.h>
#include <cstdint>
#include <math.h>

#define BB 4
#define SS 2048
#define DD 2048
#define XR (BB * SS)
typedef __half h16;

// ---------------- scratch ----------------
__device__ h16  g_x16[(size_t)XR*DD];
__device__ h16  g_w16[3][(size_t)DD*DD];         // fp16 W, natural [K,N]
__device__ h16  g_QKV[3][(size_t)XR*DD];
__device__ float g_P[(size_t)BB*SS*SS];
__device__ h16  g_Ph[(size_t)BB*SS*SS];

// ---------------- helpers ----------------
__device__ __forceinline__ uint32_t smem_u32(const void* p) {
    uint32_t a;
    asm("{ .reg .u64 t; cvta.to.shared.u64 t, %1; cvt.u32.u64 %0, t; }" : "=r"(a) : "l"(p));
    return a;
}
__device__ __forceinline__ void cp16(uint32_t dst, const void* src) {
    asm volatile("cp.async.cg.shared.global [%0], [%1], 16;" :: "r"(dst), "l"(src));
}
__device__ __forceinline__ void ldm4(uint32_t* r, uint32_t addr) {
    asm volatile("ldmatrix.sync.aligned.m8n8.x4.shared.b16 {%0,%1,%2,%3}, [%4];"
                 : "=r"(r[0]), "=r"(r[1]), "=r"(r[2]), "=r"(r[3]) : "r"(addr));
}
__device__ __forceinline__ void ldm4t(uint32_t* r, uint32_t addr) {
    asm volatile("ldmatrix.sync.aligned.m8n8.x4.trans.shared.b16 {%0,%1,%2,%3}, [%4];"
                 : "=r"(r[0]), "=r"(r[1]), "=r"(r[2]), "=r"(r[3]) : "r"(addr));
}
__device__ __forceinline__ void mma_f16(float c[4], const uint32_t a[4],
                                        uint32_t b0, uint32_t b1) {
    asm volatile(
        "mma.sync.aligned.m16n8k16.row.col.f32.f16.f16.f32 "
        "{%0,%1,%2,%3}, {%4,%5,%6,%7}, {%8,%9}, {%0,%1,%2,%3};"
        : "+f"(c[0]), "+f"(c[1]), "+f"(c[2]), "+f"(c[3])
        : "r"(a[0]), "r"(a[1]), "r"(a[2]), "r"(a[3]), "r"(b0), "r"(b1));
}
__device__ __forceinline__ uint32_t pack2(h16 a, h16 b) {
    return (uint32_t)__half_as_ushort(a) | ((uint32_t)__half_as_ushort(b) << 16);
}
__device__ __forceinline__ void gdc_wait() {
    asm volatile("griddepcontrol.wait;" ::: "memory");
}
__device__ __forceinline__ void gdc_launch() {
    asm volatile("griddepcontrol.launch_dependents;" ::: "memory");
}

// ---------------- GEMM geometry: CTA 128x128, warp 64x32, BK=64, 3 stages ----
#define RST 144                       // A row: 128B data + 16B pad
#define RSTB 272                      // trans-B row: 256B data + 16B pad
#define A_B (128 * RST)               // 18432
#define OB_OFF A_B
#define STG_NT (2 * A_B)              // 36864
#define STG_TR (A_B + 64 * RSTB)      // 35840
#define NST 3
#define SMEM_G (NST * STG_NT)         // 110592 -> 2 CTAs/SM

// C[z+ZOFF] = alpha * A[z+ZOFF] @ op(B[z+ZOFF]);  A: [M,K] rows fp16.
// BTRANS=0: B is [N,K] rows. BTRANS=1: B is [K,N] rows (trans-ldmatrix).
// EPI 0: fp32 to Cf.  EPI 1: fp16 to Ch.
// MODE 0: dense. MODE 1: causal skip (n0 > m0). MODE 2: K truncated at m0+128.
template<int EPI, int MODE, int BTRANS, int ZOFF>
__global__ void __launch_bounds__(256, 2)
gemm_f16(const h16* __restrict__ A, const h16* __restrict__ B,
         float* __restrict__ Cf, h16* __restrict__ Ch,
         int M, int N, int K, size_t sA, size_t sB, size_t sC, float alpha)
{
    constexpr int STG_B = BTRANS ? STG_TR : STG_NT;
    int by = blockIdx.y;
    if (MODE == 1 || MODE == 2) by = gridDim.y - 1 - by;
    const int m0 = by * 128;
    const int n0 = blockIdx.x * 128;
    const int z  = blockIdx.z + ZOFF;
    if (MODE == 1 && n0 > m0) { gdc_launch(); return; }
    int KT = K / 64;
    if (MODE == 2) { int kmax = m0 + 128; if (kmax < K) KT = kmax / 64; }

    extern __shared__ char smem[];
    const uint32_t sbase = smem_u32(smem);
    const int tid  = threadIdx.x;
    const int lane = tid & 31;
    const int wid  = tid >> 5;
    const int wm   = (wid >> 2) * 64;
    const int wn   = (wid & 3) * 32;

    const h16* pA = A + (size_t)z * sA;
    const h16* pB = B + (size_t)z * sB;

    auto load_stage = [&](int s, int kt) {
        if (kt < KT) {
            const uint32_t st = sbase + (uint32_t)s * STG_B;
            const size_t k0 = (size_t)kt * 64;
#pragma unroll
            for (int i = 0; i < 4; i++) {          // A: 128 rows x 8 segs
                const int slot = tid + i * 256;
                const int row = slot >> 3;
                const int seg = slot & 7;
                cp16(st + (uint32_t)(row * RST + seg * 16),
                     pA + (size_t)(m0 + row) * K + k0 + seg * 8);
            }
            if (BTRANS) {
#pragma unroll
                for (int i = 0; i < 4; i++) {      // B: 64 k-rows x 16 segs
                    const int slot = tid + i * 256;
                    const int row = slot >> 4;
                    const int seg = slot & 15;
                    cp16(st + OB_OFF + (uint32_t)(row * RSTB + seg * 16),
                         pB + (k0 + row) * (size_t)N + n0 + seg * 8);
                }
            } else {
#pragma unroll
                for (int i = 0; i < 4; i++) {      // B: 128 n-rows x 8 segs
                    const int slot = tid + i * 256;
                    const int row = slot >> 3;
                    const int seg = slot & 7;
                    cp16(st + OB_OFF + (uint32_t)(row * RST + seg * 16),
                         pB + (size_t)(n0 + row) * K + k0 + seg * 8);
                }
            }
        }
        asm volatile("cp.async.commit_group;" ::: "memory");
    };

    // ldmatrix lane addressing
    const int arow = lane & 15;
    const int akh  = lane >> 4;
    const uint32_t aoff = (uint32_t)((wm + arow) * RST + akh * 16);
    const int nrow = (lane & 7) + ((lane >> 4) << 3);
    const int bkh  = (lane >> 3) & 1;
    const uint32_t boffN = (uint32_t)((wn + nrow) * RST + bkh * 16);
    const int btrow = (lane & 7) + (((lane >> 3) & 1) << 3);
    const uint32_t boffT = (uint32_t)(btrow * RSTB + (((lane >> 4) << 3) + wn) * 2);

    float acc[4][4][4];
#pragma unroll
    for (int i = 0; i < 4; i++)
#pragma unroll
        for (int j = 0; j < 4; j++)
#pragma unroll
            for (int q = 0; q < 4; q++) acc[i][j][q] = 0.0f;

    gdc_wait();
    load_stage(0, 0);
    load_stage(1, 1);

    for (int it = 0; it < KT; it++) {
        const int s = it % NST;
        asm volatile("cp.async.wait_group 1;" ::: "memory");
        __syncthreads();
        load_stage((it + 2) % NST, it + 2);
        const uint32_t stg = sbase + (uint32_t)s * STG_B;
#pragma unroll
        for (int ks = 0; ks < 4; ks++) {
            uint32_t a[4][4], b[4][2];
#pragma unroll
            for (int mt = 0; mt < 4; mt++)
                ldm4(a[mt], stg + aoff + mt * (16 * RST) + ks * 32);
#pragma unroll
            for (int ntp = 0; ntp < 2; ntp++) {
                uint32_t t[4];
                if (BTRANS)
                    ldm4t(t, stg + OB_OFF + boffT + ks * (16 * RSTB) + ntp * 32);
                else
                    ldm4(t, stg + OB_OFF + boffN + ntp * (16 * RST) + ks * 32);
                b[2*ntp][0] = t[0]; b[2*ntp][1] = t[1];
                b[2*ntp+1][0] = t[2]; b[2*ntp+1][1] = t[3];
            }
#pragma unroll
            for (int mt = 0; mt < 4; mt++)
#pragma unroll
                for (int nt = 0; nt < 4; nt++)
                    mma_f16(acc[mt][nt], a[mt], b[nt][0], b[nt][1]);
        }
    }

    gdc_launch();

    // ---- epilogue ----
    const int r0 = wm + (lane >> 2);
    const int c0 = wn + (lane & 3) * 2;
#pragma unroll
    for (int mt = 0; mt < 4; mt++) {
#pragma unroll
        for (int nt = 0; nt < 4; nt++) {
            const int row = m0 + r0 + mt * 16;
            const int col = n0 + c0 + nt * 8;
            const float v0 = acc[mt][nt][0] * alpha, v1 = acc[mt][nt][1] * alpha;
            const float v2 = acc[mt][nt][2] * alpha, v3 = acc[mt][nt][3] * alpha;
            const size_t o0 = (size_t)z * sC + (size_t)row * N + col;
            const size_t o1 = (size_t)z * sC + (size_t)(row + 8) * N + col;
            if (EPI == 0) {
                Cf[o0] = v0; Cf[o0 + 1] = v1;
                Cf[o1] = v2; Cf[o1 + 1] = v3;
            } else {
                *reinterpret_cast<uint32_t*>(Ch + o0) =
                    pack2(__float2half_rn(v0), __float2half_rn(v1));
                *reinterpret_cast<uint32_t*>(Ch + o1) =
                    pack2(__float2half_rn(v2), __float2half_rn(v3));
            }
        }
    }
}

// ---------------- conversion (x + 3 W fused) / softmax ----------------
__global__ __launch_bounds__(256) void convert_all_kernel(
    const float* __restrict__ x, const float* __restrict__ W0,
    const float* __restrict__ W1, const float* __restrict__ W2,
    h16* __restrict__ x16, h16* __restrict__ w16)
{
    const int zz = blockIdx.z;
    const float* in;
    h16* out;
    size_t n4;
    if (zz == 0) { in = x;  out = x16;                          n4 = (size_t)XR * DD / 4; }
    else {
        in  = (zz == 1) ? W0 : (zz == 2) ? W1 : W2;
        out = w16 + (size_t)(zz - 1) * DD * DD;
        n4  = (size_t)DD * DD / 4;
    }
    for (size_t i = (size_t)blockIdx.x * 256 + threadIdx.x; i < n4; i += (size_t)gridDim.x * 256) {
        const float4 v = reinterpret_cast<const float4*>(in)[i];
        uint2 o;
        o.x = pack2(__float2half_rn(v.x), __float2half_rn(v.y));
        o.y = pack2(__float2half_rn(v.z), __float2half_rn(v.w));
        reinterpret_cast<uint2*>(out)[i] = o;
    }
    gdc_launch();
}

// causal softmax, warp-shuffle reductions, float4 I/O. One block per row.
__global__ __launch_bounds__(256) void softmax_kernel(
    const float* __restrict__ P, h16* __restrict__ Ph)
{
    const int row = blockIdx.x & (SS - 1);
    const int b   = blockIdx.x >> 11;
    const size_t base = ((size_t)b * SS + row) * SS;
    const int L = row + 1;
    const int tid  = threadIdx.x;
    const int lane = tid & 31;
    const int wrp  = tid >> 5;

    gdc_wait();
    const float4* P4 = reinterpret_cast<const float4*>(P + base);
    float4 va = P4[tid];
    float4 vb = P4[tid + 256];
    const int e0 = tid * 4;
    const int e1 = 1024 + tid * 4;

    float v[8] = {va.x, va.y, va.z, va.w, vb.x, vb.y, vb.z, vb.w};
    float m = -INFINITY;
#pragma unroll
    for (int q = 0; q < 4; q++) if (e0 + q < L) m = fmaxf(m, v[q]);
#pragma unroll
    for (int q = 0; q < 4; q++) if (e1 + q < L) m = fmaxf(m, v[4 + q]);

    __shared__ float red[8];
#pragma unroll
    for (int o = 16; o > 0; o >>= 1) m = fmaxf(m, __shfl_xor_sync(0xFFFFFFFFu, m, o));
    if (lane == 0) red[wrp] = m;
    __syncthreads();
#pragma unroll
    for (int w = 0; w < 8; w++) m = fmaxf(m, red[w]);
    __syncthreads();

    float sum = 0.0f;
#pragma unroll
    for (int q = 0; q < 4; q++) {
        v[q]     = (e0 + q < L) ? __expf(v[q] - m)     : 0.0f;
        v[4 + q] = (e1 + q < L) ? __expf(v[4 + q] - m) : 0.0f;
        sum += v[q] + v[4 + q];
    }
#pragma unroll
    for (int o = 16; o > 0; o >>= 1) sum += __shfl_xor_sync(0xFFFFFFFFu, sum, o);
    if (lane == 0) red[wrp] = sum;
    __syncthreads();
    sum = 0.0f;
#pragma unroll
    for (int w = 0; w < 8; w++) sum += red[w];
    const float inv = 1.0f / sum;
    gdc_launch();

    uint2* O4 = reinterpret_cast<uint2*>(Ph + base);
    uint2 oa, ob;
    oa.x = pack2(__float2half_rn(v[0] * inv), __float2half_rn(v[1] * inv));
    oa.y = pack2(__float2half_rn(v[2] * inv), __float2half_rn(v[3] * inv));
    ob.x = pack2(__float2half_rn(v[4] * inv), __float2half_rn(v[5] * inv));
    ob.y = pack2(__float2half_rn(v[6] * inv), __float2half_rn(v[7] * inv));
    O4[tid] = oa;
    O4[tid + 256] = ob;
}

// ---------------- PDL launch helper ----------------
static void launch_pdl(const void* func, dim3 grid, dim3 block, size_t smem,
                       void** args, cudaStream_t st)
{
    cudaLaunchConfig_t cfg = {};
    cfg.gridDim = grid;
    cfg.blockDim = block;
    cfg.dynamicSmemBytes = smem;
    cfg.stream = st;
    cudaLaunchAttribute attr[1];
    attr[0].id = cudaLaunchAttributeProgrammaticStreamSerialization;
    attr[0].val.programmaticStreamSerializationAllowed = 1;
    cfg.attrs = attr;
    cfg.numAttrs = 1;
    if (cudaLaunchKernelExC(&cfg, func, args) != cudaSuccess) {
        cudaLaunchKernel(func, grid, block, args, smem, st);
    }
}

// ---------------- launch ----------------
extern "C" void kernel_launch(void* const* d_in, const int* in_sizes, int n_in,
                              void* d_out, int out_size)
{
    const float* x  = (const float*)d_in[0];
    const float* Wq = (const float*)d_in[1];
    const float* Wk = (const float*)d_in[2];
    const float* Wv = (const float*)d_in[3];
    float* out = (float*)d_out;

    h16 *x16, *w16, *QKV, *Ph;
    float* P;
    cudaGetSymbolAddress((void**)&x16, g_x16);
    cudaGetSymbolAddress((void**)&w16, g_w16);
    cudaGetSymbolAddress((void**)&QKV, g_QKV);
    cudaGetSymbolAddress((void**)&P,   g_P);
    cudaGetSymbolAddress((void**)&Ph,  g_Ph);

    cudaFuncSetAttribute(gemm_f16<1,0,1,0>, cudaFuncAttributeMaxDynamicSharedMemorySize, SMEM_G);
    cudaFuncSetAttribute(gemm_f16<1,0,1,2>, cudaFuncAttributeMaxDynamicSharedMemorySize, SMEM_G);
    cudaFuncSetAttribute(gemm_f16<0,1,0,0>, cudaFuncAttributeMaxDynamicSharedMemorySize, SMEM_G);
    cudaFuncSetAttribute(gemm_f16<0,2,1,0>, cudaFuncAttributeMaxDynamicSharedMemorySize, SMEM_G);

    // one-time side stream + events (reused every call; no device-mem allocs)
    static cudaStream_t s2 = nullptr;
    static cudaEvent_t evFork = nullptr, evJoin = nullptr;
    if (s2 == nullptr) {
        cudaStreamCreateWithFlags(&s2, cudaStreamNonBlocking);
        cudaEventCreateWithFlags(&evFork, cudaEventDisableTiming);
        cudaEventCreateWithFlags(&evJoin, cudaEventDisableTiming);
    }

    size_t WSZ = (size_t)DD * DD;
    size_t QSZ = (size_t)XR * DD;
    const float scale = 1.0f / sqrtf((float)DD);
    h16* nullh = nullptr;
    float* nullf = nullptr;

    // 1. fp32 -> fp16 conversions (x and all W) on stream 0
    convert_all_kernel<<<dim3(2048, 1, 4), 256>>>(x, Wq, Wk, Wv, x16, w16);

    // fork: s2 waits on conversions
    cudaEventRecord(evFork, 0);
    cudaStreamWaitEvent(s2, evFork, 0);

    // 2a. V projection (z=2) on side stream — needed only by PV
    {
        int M = XR, N = DD, K = DD;
        size_t sA = 0, sB = WSZ, sC = QSZ;
        float alpha = 1.0f;
        void* args[] = {&x16, &w16, &nullf, &QKV, &M, &N, &K, &sA, &sB, &sC, &alpha};
        launch_pdl((const void*)gemm_f16<1,0,1,2>, dim3(DD/128, XR/128, 1), 256, SMEM_G, args, s2);
    }

    // 2b. Q,K projections (z=0,1) on stream 0
    {
        int M = XR, N = DD, K = DD;
        size_t sA = 0, sB = WSZ, sC = QSZ;
        float alpha = 1.0f;
        void* args[] = {&x16, &w16, &nullf, &QKV, &M, &N, &K, &sA, &sB, &sC, &alpha};
        launch_pdl((const void*)gemm_f16<1,0,1,0>, dim3(DD/128, XR/128, 2), 256, SMEM_G, args, 0);
    }

    // 3. scores: P[b] = scale * Q[b] @ K[b]^T (causal skip) on stream 0
    {
        int M = SS, N = SS, K = DD;
        size_t sA = (size_t)SS*DD, sB = (size_t)SS*DD, sC = (size_t)SS*SS;
        float alpha = scale;
        const h16* Qp = QKV;
        const h16* Kp = QKV + QSZ;
        void* args[] = {&Qp, &Kp, &P, &nullh, &M, &N, &K, &sA, &sB, &sC, &alpha};
        launch_pdl((const void*)gemm_f16<0,1,0,0>, dim3(SS/128, SS/128, BB), 256, SMEM_G, args, 0);
    }

    // 4. causal softmax -> fp16 P on stream 0
    {
        const float* Pp = P;
        void* args[] = {&Pp, &Ph};
        launch_pdl((const void*)softmax_kernel, dim3(BB * SS), 256, 0, args, 0);
    }

    // join: stream 0 waits for V projection
    cudaEventRecord(evJoin, s2);
    cudaStreamWaitEvent(0, evJoin, 0);

    // 5. out[b] = P[b] @ V[b] (K truncated at diagonal) on stream 0
    {
        int M = SS, N = DD, K = SS;
        size_t sA = (size_t)SS*SS, sB = (size_t)SS*DD, sC = (size_t)SS*DD;
        float alpha = 1.0f;
        const h16* Pp = Ph;
        const h16* Vp = QKV + 2*QSZ;
        void* args[] = {&Pp, &Vp, &out, &nullh, &M, &N, &K, &sA, &sB, &sC, &alpha};
        // plain launch: PDL-wait here would pair with softmax, but the event join
        // already orders V; keep PDL for the softmax edge.
        launch_pdl((const void*)gemm_f16<0,2,1,0>, dim3(DD/128, SS/128, BB), 256, SMEM_G, args, 0);
    }
}